// round 12
// baseline (speedup 1.0000x reference)
#include <cuda_runtime.h>
#include <cstdint>

#define BATCH 32
#define CIN   256
#define COUT  256
#define HH_   56
#define WW_   56
#define HW_   (HH_*WW_)
#define NPOS  (BATCH*HW_)

// ---------------- device scratch ----------------
__device__ uint4 g_xpack[NPOS * 2];        // [pos][2]: 8 u32 sign bits (bit=1 iff x>=0)
__device__ uint4 g_wpack[COUT * 9 * 2];    // [cout*9+tap][2]

// ---------------- fused pack kernel ----------------
__global__ void pack_all_kernel(const float* __restrict__ x,
                                const float* __restrict__ wgt) {
    if (blockIdx.x < 392) {                       // 392*256 == NPOS exactly
        int pos = blockIdx.x * 256 + threadIdx.x;
        int b  = pos / HW_;
        int hw = pos - b * HW_;
        const float* xp = x + (size_t)b * CIN * HW_ + hw;
        uint32_t wds[8];
        #pragma unroll
        for (int k = 0; k < 8; ++k) {
            uint32_t wd = 0;
            #pragma unroll
            for (int i = 0; i < 32; ++i) {
                float v = xp[(size_t)(k * 32 + i) * HW_];
                wd |= (v >= 0.0f ? 1u : 0u) << i;
            }
            wds[k] = wd;
        }
        g_xpack[pos * 2 + 0] = make_uint4(wds[0], wds[1], wds[2], wds[3]);
        g_xpack[pos * 2 + 1] = make_uint4(wds[4], wds[5], wds[6], wds[7]);
    } else {
        int idx = (blockIdx.x - 392) * 256 + threadIdx.x;   // cout*9+tap
        if (idx >= COUT * 9) return;
        int cout = idx / 9;
        int tap  = idx - cout * 9;
        const float* wp = wgt + (size_t)cout * CIN * 9 + tap;
        uint32_t wds[8];
        #pragma unroll
        for (int k = 0; k < 8; ++k) {
            uint32_t wd = 0;
            #pragma unroll
            for (int i = 0; i < 32; ++i) {
                float v = wp[(size_t)(k * 32 + i) * 9];
                wd |= (v >= 0.0f ? 1u : 0u) << i;
            }
            wds[k] = wd;
        }
        g_wpack[idx * 2 + 0] = make_uint4(wds[0], wds[1], wds[2], wds[3]);
        g_wpack[idx * 2 + 1] = make_uint4(wds[4], wds[5], wds[6], wds[7]);
    }
}

// ---------------- main conv: half cin split, TWO independent column streams --
// Block = 256 threads = 8 warps. Lane = half*16 + csub.
//   csub (0..15) -> cout = bz*128 + wid*16 + csub;  half -> cin words 4h..4h+3.
// Per thread: stream L covers outputs w=0..27 (x cols 0..28),
//             stream R covers outputs w=28..55 (x cols 27..55).
__global__ void __launch_bounds__(256, 3)
bconv_pop_kernel(const float* __restrict__ bias, float* __restrict__ out) {
    __shared__ uint4 xs[3 * WW_ * 2];     // [row][v][half]

    const int tid  = threadIdx.x;
    const int lane = tid & 31;
    const int wid  = tid >> 5;
    const int half = lane >> 4;
    const int csub = lane & 15;
    const int h    = blockIdx.x;
    const int b    = blockIdx.y;
    const int cout = blockIdx.z * 128 + wid * 16 + csub;

    const bool rv0 = (h > 0), rv2 = (h < HH_ - 1);

    // ---- stage x (3 rows x 56 cols x 2 halves), zero-fill invalid rows ----
    for (int i = tid; i < 3 * WW_ * 2; i += 256) {
        int row = i / (WW_ * 2);
        int rem = i - row * (WW_ * 2);
        int v = rem >> 1, j = rem & 1;
        int rin = h - 1 + row;
        uint4 val = make_uint4(0u, 0u, 0u, 0u);
        if (rin >= 0 && rin < HH_)
            val = g_xpack[((size_t)(b * HH_ + rin) * WW_ + v) * 2 + j];
        xs[(row * WW_ + v) * 2 + j] = val;
    }

    // ---- per-lane half-weights in registers (36 regs) ----
    uint32_t wreg[9][4];
    #pragma unroll
    for (int t = 0; t < 9; ++t) {
        uint4 a = g_wpack[(cout * 9 + t) * 2 + half];
        wreg[t][0] = a.x; wreg[t][1] = a.y; wreg[t][2] = a.z; wreg[t][3] = a.w;
    }
    const float bv = bias[cout];

    // ---- per-half pad-correction constants ----
    int pm[3], pl[3], pr[3];
    #pragma unroll
    for (int dh = 0; dh < 3; ++dh) {
        int p0 = 0, p1 = 0, p2 = 0;
        #pragma unroll
        for (int k = 0; k < 4; ++k) {
            p0 += __popc(wreg[dh * 3 + 0][k]);
            p1 += __popc(wreg[dh * 3 + 1][k]);
            p2 += __popc(wreg[dh * 3 + 2][k]);
        }
        pm[dh] = p0 + p1 + p2; pl[dh] = p1 + p2; pr[dh] = p0 + p1;
    }
    const int nrows = (int)rv0 + 1 + (int)rv2;
    const int cmid   = 384 * nrows + 2 * ((rv0 ? 0 : pm[0]) + (rv2 ? 0 : pm[2]));
    const int cleft  = 256 * nrows + 2 * ((rv0 ? 0 : pl[0]) + (rv2 ? 0 : pl[2]));
    const int cright = 256 * nrows + 2 * ((rv0 ? 0 : pr[0]) + (rv2 ? 0 : pr[2]));

    __syncthreads();

    float* obase = out + ((size_t)(b * COUT + cout) * HH_ + h) * WW_;

    // one full 9-product step for stream at x column vv into ring rg (u compile-time)
    #define STEP(rg, vv, u) do {                                                \
        int addn = 0, addm = 0, addo = 0;                                       \
        _Pragma("unroll")                                                       \
        for (int row = 0; row < 3; ++row) {                                     \
            uint4 xa = xs[(row * WW_ + (vv)) * 2 + half];                       \
            uint32_t xw[4] = {xa.x, xa.y, xa.z, xa.w};                          \
            _Pragma("unroll")                                                   \
            for (int k = 0; k < 4; ++k) {                                       \
                addn += __popc(xw[k] ^ wreg[row * 3 + 0][k]);                   \
                addm += __popc(xw[k] ^ wreg[row * 3 + 1][k]);                   \
                addo += __popc(xw[k] ^ wreg[row * 3 + 2][k]);                   \
            }                                                                   \
        }                                                                       \
        rg[((u) + 1) & 3] += addn;                                              \
        rg[(u) & 3]       += addm;                                              \
        rg[((u) + 3) & 3] += addo;                                              \
    } while (0)

    // complete output w from rg[slot] with constant c; pair-store or stash
    #define COMPLETE(rg, slot, c, wv, fstash, dostore) do {                     \
        int comb = (c) - 2 * rg[slot];                                          \
        comb += __shfl_xor_sync(0xffffffffu, comb, 16);                         \
        rg[slot] = 0;                                                           \
        float f = (float)comb + bv;                                             \
        if (dostore) {                                                          \
            if (half == 0)                                                      \
                *(float2*)(obase + (wv) - 1) = make_float2(fstash, f);          \
        } else {                                                                \
            fstash = f;                                                         \
        }                                                                       \
    } while (0)

    int ringL[4] = {0, 0, 0, 0};
    int ringR[4] = {0, 0, 0, 0};
    float fLa = 0.0f, fRa = 0.0f;

    // R prefix: x col 27, dw=0 -> output w=28 (slot 0)
    {
        int a = 0;
        #pragma unroll
        for (int row = 0; row < 3; ++row) {
            uint4 xa = xs[(row * WW_ + 27) * 2 + half];
            uint32_t xw[4] = {xa.x, xa.y, xa.z, xa.w};
            #pragma unroll
            for (int k = 0; k < 4; ++k)
                a += __popc(xw[k] ^ wreg[row * 3 + 0][k]);
        }
        ringR[0] = a;
    }

    for (int i0 = 0; i0 < 7; ++i0) {
        const int ib = i0 * 4;
        #pragma unroll
        for (int u = 0; u < 4; ++u) {
            const int i = ib + u;          // L: v=i ; R: v=28+i
            STEP(ringL, i, u);
            STEP(ringR, 28 + i, u);

            const int slot = (u + 3) & 3;
            if (u == 0) {
                if (i0 == 0) {
                    ringL[3] = 0;          // w=-1 garbage
                    ringR[3] = 0;          // w=27 (belongs to L; recomputed in fixup)
                } else {
                    // i even -> w odd -> store pair
                    COMPLETE(ringL, slot, cmid, i - 1,  fLa, true);
                    COMPLETE(ringR, slot, cmid, 27 + i, fRa, true);
                }
            } else if (u == 1) {
                // w even -> stash
                const int cL = (i0 == 0) ? cleft : cmid;   // w==0 edge
                COMPLETE(ringL, slot, cL,   i - 1,  fLa, false);
                COMPLETE(ringR, slot, cmid, 27 + i, fRa, false);
            } else if (u == 2) {
                COMPLETE(ringL, slot, cmid, i - 1,  fLa, true);
                COMPLETE(ringR, slot, cmid, 27 + i, fRa, true);
            } else {
                COMPLETE(ringL, slot, cmid, i - 1,  fLa, false);
                COMPLETE(ringR, slot, cmid, 27 + i, fRa, false);
            }
        }
    }

    // L postfix: w=27 still needs x col 28, dw=2; then complete (slot 3, cmid)
    {
        int a = 0;
        #pragma unroll
        for (int row = 0; row < 3; ++row) {
            uint4 xa = xs[(row * WW_ + 28) * 2 + half];
            uint32_t xw[4] = {xa.x, xa.y, xa.z, xa.w};
            #pragma unroll
            for (int k = 0; k < 4; ++k)
                a += __popc(xw[k] ^ wreg[row * 3 + 2][k]);
        }
        ringL[3] += a;
        COMPLETE(ringL, 3, cmid, 27, fLa, true);
    }
    // R postfix: w=55 (edge, slot 3, cright)
    COMPLETE(ringR, 3, cright, 55, fRa, true);

    #undef STEP
    #undef COMPLETE
}

// ---------------------------------------------------------------------------
extern "C" void kernel_launch(void* const* d_in, const int* in_sizes, int n_in,
                              void* d_out, int out_size) {
    const float* x    = (const float*)d_in[0];
    const float* wgt  = (const float*)d_in[1];
    const float* bias = (const float*)d_in[2];
    float* out = (float*)d_out;

    pack_all_kernel<<<401, 256>>>(x, wgt);
    dim3 grid(HH_, BATCH, 2);
    bconv_pop_kernel<<<grid, 256>>>(bias, out);
}

// round 13
// speedup vs baseline: 1.0555x; 1.0555x over previous
#include <cuda_runtime.h>
#include <cstdint>

#define BATCH 32
#define CIN   256
#define COUT  256
#define HH_   56
#define WW_   56
#define HW_   (HH_*WW_)
#define NPOS  (BATCH*HW_)

// ---------------- device scratch ----------------
__device__ uint4 g_xpack[NPOS * 2];        // [pos][2]: 8 u32 sign bits (bit=1 iff x>=0)
__device__ uint4 g_wpack[COUT * 9 * 2];    // [cout*9+tap][2]

// ---------------- fused pack kernel ----------------
__global__ void pack_all_kernel(const float* __restrict__ x,
                                const float* __restrict__ wgt) {
    if (blockIdx.x < 392) {                       // 392*256 == NPOS exactly
        int pos = blockIdx.x * 256 + threadIdx.x;
        int b  = pos / HW_;
        int hw = pos - b * HW_;
        const float* xp = x + (size_t)b * CIN * HW_ + hw;
        uint32_t wds[8];
        #pragma unroll
        for (int k = 0; k < 8; ++k) {
            uint32_t wd = 0;
            #pragma unroll
            for (int i = 0; i < 32; ++i) {
                float v = xp[(size_t)(k * 32 + i) * HW_];
                wd |= (v >= 0.0f ? 1u : 0u) << i;
            }
            wds[k] = wd;
        }
        g_xpack[pos * 2 + 0] = make_uint4(wds[0], wds[1], wds[2], wds[3]);
        g_xpack[pos * 2 + 1] = make_uint4(wds[4], wds[5], wds[6], wds[7]);
    } else {
        int idx = (blockIdx.x - 392) * 256 + threadIdx.x;   // cout*9+tap
        if (idx >= COUT * 9) return;
        int cout = idx / 9;
        int tap  = idx - cout * 9;
        const float* wp = wgt + (size_t)cout * CIN * 9 + tap;
        uint32_t wds[8];
        #pragma unroll
        for (int k = 0; k < 8; ++k) {
            uint32_t wd = 0;
            #pragma unroll
            for (int i = 0; i < 32; ++i) {
                float v = wp[(size_t)(k * 32 + i) * 9];
                wd |= (v >= 0.0f ? 1u : 0u) << i;
            }
            wds[k] = wd;
        }
        g_wpack[idx * 2 + 0] = make_uint4(wds[0], wds[1], wds[2], wds[3]);
        g_wpack[idx * 2 + 1] = make_uint4(wds[4], wds[5], wds[6], wds[7]);
    }
}

// ---------------- main conv: half cin split, occ-4, float2 stores ------------
// Block = 256 threads = 8 warps. Lane = half*16 + csub.
//   csub (0..15) -> cout = bz*128 + wid*16 + csub;  half -> cin words 4h..4h+3.
// Block computes one (b, h) output row for 128 couts.
__global__ void __launch_bounds__(256, 4)
bconv_pop_kernel(const float* __restrict__ bias, float* __restrict__ out) {
    __shared__ uint4 xs[3 * WW_ * 2];     // [row][v][half]

    const int tid  = threadIdx.x;
    const int lane = tid & 31;
    const int wid  = tid >> 5;
    const int half = lane >> 4;
    const int csub = lane & 15;
    const int h    = blockIdx.x;
    const int b    = blockIdx.y;
    const int cout = blockIdx.z * 128 + wid * 16 + csub;

    const bool rv0 = (h > 0), rv2 = (h < HH_ - 1);

    // ---- stage x (3 rows x 56 cols x 2 halves), zero-fill invalid rows ----
    for (int i = tid; i < 3 * WW_ * 2; i += 256) {
        int row = i / (WW_ * 2);
        int rem = i - row * (WW_ * 2);
        int v = rem >> 1, j = rem & 1;
        int rin = h - 1 + row;
        uint4 val = make_uint4(0u, 0u, 0u, 0u);
        if (rin >= 0 && rin < HH_)
            val = g_xpack[((size_t)(b * HH_ + rin) * WW_ + v) * 2 + j];
        xs[(row * WW_ + v) * 2 + j] = val;
    }

    // ---- per-lane half-weights in registers (36 regs) ----
    uint32_t wreg[9][4];
    #pragma unroll
    for (int t = 0; t < 9; ++t) {
        uint4 a = g_wpack[(cout * 9 + t) * 2 + half];
        wreg[t][0] = a.x; wreg[t][1] = a.y; wreg[t][2] = a.z; wreg[t][3] = a.w;
    }
    const float bv = bias[cout];

    // ---- per-half pad-correction constants ----
    int pm[3], pl[3], pr[3];
    #pragma unroll
    for (int dh = 0; dh < 3; ++dh) {
        int p0 = 0, p1 = 0, p2 = 0;
        #pragma unroll
        for (int k = 0; k < 4; ++k) {
            p0 += __popc(wreg[dh * 3 + 0][k]);
            p1 += __popc(wreg[dh * 3 + 1][k]);
            p2 += __popc(wreg[dh * 3 + 2][k]);
        }
        pm[dh] = p0 + p1 + p2; pl[dh] = p1 + p2; pr[dh] = p0 + p1;
    }
    const int nrows = (int)rv0 + 1 + (int)rv2;
    const int cmid   = 384 * nrows + 2 * ((rv0 ? 0 : pm[0]) + (rv2 ? 0 : pm[2]));
    const int cleft  = 256 * nrows + 2 * ((rv0 ? 0 : pl[0]) + (rv2 ? 0 : pl[2]));
    const int cright = 256 * nrows + 2 * ((rv0 ? 0 : pr[0]) + (rv2 ? 0 : pr[2]));

    __syncthreads();

    float* obase = out + ((size_t)(b * COUT + cout) * HH_ + h) * WW_;

    int ring[4] = {0, 0, 0, 0};
    float fb0 = 0.0f;

    // v = input column. x col v feeds outputs w = v+1-dw, dw in {0,1,2}.
    // Output w completes at end of step v = w+1; w parity = !(u parity).
    for (int v0 = 0; v0 < 7; ++v0) {
        #pragma unroll
        for (int u = 0; u < 8; ++u) {
            const int v = v0 * 8 + u;
            int addn = 0, addm = 0, addo = 0;
            #pragma unroll
            for (int row = 0; row < 3; ++row) {
                uint4 xa = xs[(row * WW_ + v) * 2 + half];
                uint32_t xw[4] = {xa.x, xa.y, xa.z, xa.w};
                #pragma unroll
                for (int k = 0; k < 4; ++k) {
                    addn += __popc(xw[k] ^ wreg[row * 3 + 0][k]);
                    addm += __popc(xw[k] ^ wreg[row * 3 + 1][k]);
                    addo += __popc(xw[k] ^ wreg[row * 3 + 2][k]);
                }
            }
            ring[(u + 1) & 3] += addn;      // w = v+1
            ring[u & 3]       += addm;      // w = v
            ring[(u + 3) & 3] += addo;      // w = v-1 (completes now)

            if (u == 0) {
                if (v0 == 0) {
                    ring[3] = 0;            // discard w=-1 garbage
                } else {
                    // w = 8*v0 - 1 (odd) -> pair store
                    int comb = cmid - 2 * ring[3];
                    comb += __shfl_xor_sync(0xffffffffu, comb, 16);
                    ring[3] = 0;
                    if (half == 0)
                        *(float2*)(obase + v0 * 8 - 2) =
                            make_float2(fb0, (float)comb + bv);
                }
            } else {
                const int slot = (u + 3) & 3;
                int c = cmid;
                if (u == 1) c = (v0 == 0) ? cleft : cmid;   // w==0 edge
                int comb = c - 2 * ring[slot];
                comb += __shfl_xor_sync(0xffffffffu, comb, 16);
                ring[slot] = 0;
                if (u & 1) {
                    // w = v-1 even -> stash
                    fb0 = (float)comb + bv;
                } else {
                    // w = v-1 odd -> pair store at w-1
                    if (half == 0)
                        *(float2*)(obase + v0 * 8 + u - 2) =
                            make_float2(fb0, (float)comb + bv);
                }
            }
        }
    }
    // tail: w = 55 (odd, edge) sits in slot 3; fb0 holds w=54
    {
        int comb = cright - 2 * ring[3];
        comb += __shfl_xor_sync(0xffffffffu, comb, 16);
        if (half == 0)
            *(float2*)(obase + 54) = make_float2(fb0, (float)comb + bv);
    }
}

// ---------------------------------------------------------------------------
extern "C" void kernel_launch(void* const* d_in, const int* in_sizes, int n_in,
                              void* d_out, int out_size) {
    const float* x    = (const float*)d_in[0];
    const float* wgt  = (const float*)d_in[1];
    const float* bias = (const float*)d_in[2];
    float* out = (float*)d_out;

    pack_all_kernel<<<401, 256>>>(x, wgt);
    dim3 grid(HH_, BATCH, 2);
    bconv_pop_kernel<<<grid, 256>>>(bias, out);
}